// round 1
// baseline (speedup 1.0000x reference)
#include <cuda_runtime.h>

#define TS   16     // samples per block
#define NT   256    // threads per block
#define NBLK 128    // 2048 / TS

// feature offsets into the one-hot space, embedding dims, concat offsets
__constant__ int c_FOFF[9] = {0,100000,150000,150010,150013,150113,150163,151163,151187};
__constant__ int c_EDIM[9] = {16,16,8,4,8,8,8,4,4};
__constant__ int c_EOFF[9] = {0,16,32,40,44,52,60,68,72};
#define NF_LAST 151192   // index of the price column = NUM_FEATURES-1

struct P30 { const void* p[30]; };

__device__ __forceinline__ int read_id(const void* p, int i, bool is64) {
    return is64 ? (int)((const long long*)p)[i] : ((const int*)p)[i];
}

// smem floats: W-stage 32768, X 16*80, H1 4096, H2 2048, H3 1024, base 16, price 16, idx 144 ints
#define SMEM_BYTES ((32768 + 16*80 + 4096 + 2048 + 1024 + 16 + 16) * 4 + 16*9*4)

extern "C" __global__ void __launch_bounds__(NT, 1)
deepfm_kernel(P30 a, float* __restrict__ out, int B)
{
    extern __shared__ float sm[];
    float* sW     = sm;                 // up to 32768 floats (W2 is biggest)
    float* sX     = sm + 32768;         // [16][80] deep_in, padded
    float* sH1    = sX + 16*80;         // [16][256]
    float* sH2    = sH1 + 4096;         // [16][128]
    float* sH3    = sH2 + 2048;         // [16][64]
    float* sBase  = sH3 + 1024;         // [16] dense+fm logit
    float* sPrice = sBase + 16;         // [16]
    int*   sIdx   = (int*)(sPrice + 16);// [16][9]

    const int t  = threadIdx.x;
    const int s0 = blockIdx.x * TS;

    // ---- on-device input-layout detection (deterministic, data-driven) ----
    const unsigned long long* u0 = (const unsigned long long*)a.p[0];
    const bool is64 = ((u0[0] | u0[1] | u0[2] | u0[3]) < (1ULL << 20));
    const unsigned long long* u7 = (const unsigned long long*)a.p[7];
    const bool dict = (u7[0] < (1ULL << 40));   // slot7 small ints => hour (dict order)

    const void* idp[9];
    #pragma unroll
    for (int f = 0; f < 7; f++) idp[f] = a.p[f];
    const float* price;
    if (dict) { idp[7] = a.p[7]; idp[8] = a.p[8]; price = (const float*)a.p[9]; }
    else      { price = (const float*)a.p[7]; idp[7] = a.p[8]; idp[8] = a.p[9]; }

    const float* emb[9];
    #pragma unroll
    for (int f = 0; f < 9; f++) emb[f] = (const float*)a.p[10 + f];
    const float* w_dense = (const float*)a.p[19];
    const float* b_dense = (const float*)a.p[20];
    const float* fm_v    = (const float*)a.p[21];
    const float* W1 = (const float*)a.p[22];
    const float* b1 = (const float*)a.p[23];
    const float* W2 = (const float*)a.p[24];
    const float* b2 = (const float*)a.p[25];
    const float* W3 = (const float*)a.p[26];
    const float* b3 = (const float*)a.p[27];
    const float* Wo = (const float*)a.p[28];
    const float* bo = (const float*)a.p[29];

    // ---- Phase A: gather ids/price + stage W1 (77*256 = 4928 float4) ----
    if (t < TS * 9) {
        int s = t / 9, f = t - s * 9;
        sIdx[s * 9 + f] = read_id(idp[f], s0 + s, is64);
    }
    if (t >= 224 && t < 224 + TS) sPrice[t - 224] = price[s0 + (t - 224)];
    for (int i = t; i < 4928; i += NT) ((float4*)sW)[i] = ((const float4*)W1)[i];
    __syncthreads();

    // ---- Phase B: FM 2nd order + dense 1st order (half-warp per sample, E=16 lanes) ----
    {
        int w = t >> 5, lane = t & 31;
        int s = w * 2 + (lane >> 4);
        int e = lane & 15;
        float pv = sPrice[s] * 1e-3f;
        float fs = 0.f, ss = 0.f;
        #pragma unroll
        for (int f = 0; f < 9; f++) {
            int row = c_FOFF[f] + sIdx[s * 9 + f];
            float v = fm_v[row * 16 + e];
            fs += v; ss += v * v;
        }
        {
            float v = fm_v[NF_LAST * 16 + e];
            fs += pv * v; ss += pv * pv * v * v;
        }
        float val = fs * fs - ss;
        #pragma unroll
        for (int o = 8; o; o >>= 1) val += __shfl_xor_sync(0xffffffffu, val, o, 16);
        float fm = 0.5f * val;

        float dn = 0.f;
        if (e < 9)  dn = w_dense[c_FOFF[e] + sIdx[s * 9 + e]];
        if (e == 9) dn = pv * w_dense[NF_LAST];
        #pragma unroll
        for (int o = 8; o; o >>= 1) dn += __shfl_xor_sync(0xffffffffu, dn, o, 16);

        if (e == 0) sBase[s] = fm + dn + b_dense[0];
    }

    // ---- Phase C: build deep_in X[16][77] (embedding concat + price) ----
    for (int idx = t; idx < TS * 77; idx += NT) {
        int s = idx / 77, c = idx - s * 77;
        float v;
        if (c == 76) v = sPrice[s];
        else {
            int f = 8;
            #pragma unroll
            for (int k = 8; k >= 1; k--) if (c < c_EOFF[k]) f = k - 1;
            int e = c - c_EOFF[f];
            v = emb[f][sIdx[s * 9 + f] * c_EDIM[f] + e];
        }
        sX[s * 80 + c] = v;
    }
    __syncthreads();

    // ---- Layer 1: H1 = relu(X @ W1 + b1); 4 samples x 4 outs per thread ----
    {
        int jg = t & 63;          // j0 = jg*4, 256 outputs
        int sg = t >> 6;          // samples sg*4 .. sg*4+3
        int j0 = jg * 4;
        float4 bv = ((const float4*)b1)[jg];
        float acc[4][4];
        #pragma unroll
        for (int si = 0; si < 4; si++) {
            acc[si][0] = bv.x; acc[si][1] = bv.y; acc[si][2] = bv.z; acc[si][3] = bv.w;
        }
        #pragma unroll 7
        for (int i = 0; i < 77; i++) {
            float4 wv = *(const float4*)(sW + i * 256 + j0);
            #pragma unroll
            for (int si = 0; si < 4; si++) {
                float x = sX[(sg * 4 + si) * 80 + i];
                acc[si][0] += x * wv.x; acc[si][1] += x * wv.y;
                acc[si][2] += x * wv.z; acc[si][3] += x * wv.w;
            }
        }
        #pragma unroll
        for (int si = 0; si < 4; si++) {
            float4 o;
            o.x = fmaxf(acc[si][0], 0.f); o.y = fmaxf(acc[si][1], 0.f);
            o.z = fmaxf(acc[si][2], 0.f); o.w = fmaxf(acc[si][3], 0.f);
            *(float4*)(sH1 + (sg * 4 + si) * 256 + j0) = o;
        }
    }
    __syncthreads();

    // ---- stage W2 (256*128 = 8192 float4) ----
    for (int i = t; i < 8192; i += NT) ((float4*)sW)[i] = ((const float4*)W2)[i];
    __syncthreads();

    // ---- Layer 2: H2 = relu(H1 @ W2 + b2); 2 samples x 4 outs per thread ----
    {
        int jg = t & 31;          // j0 = jg*4, 128 outputs
        int sg = t >> 5;          // samples sg*2, sg*2+1
        int j0 = jg * 4;
        float4 bv = ((const float4*)b2)[jg];
        float acc[2][4];
        #pragma unroll
        for (int si = 0; si < 2; si++) {
            acc[si][0] = bv.x; acc[si][1] = bv.y; acc[si][2] = bv.z; acc[si][3] = bv.w;
        }
        #pragma unroll 8
        for (int i = 0; i < 256; i++) {
            float4 wv = *(const float4*)(sW + i * 128 + j0);
            #pragma unroll
            for (int si = 0; si < 2; si++) {
                float x = sH1[(sg * 2 + si) * 256 + i];
                acc[si][0] += x * wv.x; acc[si][1] += x * wv.y;
                acc[si][2] += x * wv.z; acc[si][3] += x * wv.w;
            }
        }
        #pragma unroll
        for (int si = 0; si < 2; si++) {
            float4 o;
            o.x = fmaxf(acc[si][0], 0.f); o.y = fmaxf(acc[si][1], 0.f);
            o.z = fmaxf(acc[si][2], 0.f); o.w = fmaxf(acc[si][3], 0.f);
            *(float4*)(sH2 + (sg * 2 + si) * 128 + j0) = o;
        }
    }
    __syncthreads();

    // ---- stage W3 (128*64 = 2048 float4) ----
    for (int i = t; i < 2048; i += NT) ((float4*)sW)[i] = ((const float4*)W3)[i];
    __syncthreads();

    // ---- Layer 3: H3 = relu(H2 @ W3 + b3); 2 samples x 2 outs per thread ----
    {
        int jg = t & 31;          // j0 = jg*2, 64 outputs
        int sg = t >> 5;          // samples sg*2, sg*2+1
        int j0 = jg * 2;
        float2 bv = ((const float2*)b3)[jg];
        float acc[2][2];
        #pragma unroll
        for (int si = 0; si < 2; si++) { acc[si][0] = bv.x; acc[si][1] = bv.y; }
        #pragma unroll 8
        for (int i = 0; i < 128; i++) {
            float2 wv = *(const float2*)(sW + i * 64 + j0);
            #pragma unroll
            for (int si = 0; si < 2; si++) {
                float x = sH2[(sg * 2 + si) * 128 + i];
                acc[si][0] += x * wv.x; acc[si][1] += x * wv.y;
            }
        }
        #pragma unroll
        for (int si = 0; si < 2; si++) {
            sH3[(sg * 2 + si) * 64 + j0    ] = fmaxf(acc[si][0], 0.f);
            sH3[(sg * 2 + si) * 64 + j0 + 1] = fmaxf(acc[si][1], 0.f);
        }
    }
    __syncthreads();

    // ---- Output: (H3 @ Wo + bo) + base; warp per 2 samples ----
    {
        int w = t >> 5, lane = t & 31;
        #pragma unroll
        for (int rep = 0; rep < 2; rep++) {
            int s = w * 2 + rep;
            float v = sH3[s * 64 + lane]      * Wo[lane]
                    + sH3[s * 64 + 32 + lane] * Wo[32 + lane];
            #pragma unroll
            for (int o = 16; o; o >>= 1) v += __shfl_xor_sync(0xffffffffu, v, o);
            if (lane == 0 && (s0 + s) < B) out[s0 + s] = v + bo[0] + sBase[s];
        }
    }
}

extern "C" void kernel_launch(void* const* d_in, const int* in_sizes, int n_in,
                              void* d_out, int out_size)
{
    (void)in_sizes; (void)n_in;
    P30 a;
    for (int i = 0; i < 30; i++) a.p[i] = d_in[i];
    cudaFuncSetAttribute(deepfm_kernel, cudaFuncAttributeMaxDynamicSharedMemorySize, SMEM_BYTES);
    deepfm_kernel<<<NBLK, NT, SMEM_BYTES>>>(a, (float*)d_out, out_size);
}

// round 2
// speedup vs baseline: 1.1734x; 1.1734x over previous
#include <cuda_runtime.h>

#define TS   16     // samples per block
#define NT   256    // threads per block
#define NBLK 128    // 2048 / TS

// feature offsets into the one-hot space, embedding dims, concat offsets
__constant__ int c_FOFF[9] = {0,100000,150000,150010,150013,150113,150163,151163,151187};
__constant__ int c_EDIM[9] = {16,16,8,4,8,8,8,4,4};
__constant__ int c_EOFF[9] = {0,16,32,40,44,52,60,68,72};
#define NF_LAST 151192   // index of the price column = NUM_FEATURES-1

struct P30 { const void* p[30]; };

typedef unsigned long long u64;

__device__ __forceinline__ void ffma2(u64 &d, u64 a, u64 b) {
    asm("fma.rn.f32x2 %0, %1, %2, %0;" : "+l"(d) : "l"(a), "l"(b));
}
__device__ __forceinline__ u64 pack2(float x) {
    u64 r; asm("mov.b64 %0, {%1, %1};" : "=l"(r) : "f"(x)); return r;
}
__device__ __forceinline__ float2 unpack2(u64 v) {
    float2 f; asm("mov.b64 {%0, %1}, %2;" : "=f"(f.x), "=f"(f.y) : "l"(v)); return f;
}
__device__ __forceinline__ int read_id(const void* p, int i, bool is64) {
    return is64 ? (int)((const long long*)p)[i] : ((const int*)p)[i];
}

extern "C" __global__ void __launch_bounds__(NT, 1)
deepfm_kernel(P30 a, float* __restrict__ out, int B)
{
    // transposed activations: [K][16 samples]
    __shared__ __align__(16) float sXT [77 * 16];
    __shared__ __align__(16) float sH1T[256 * 16];
    __shared__ __align__(16) float sH2T[128 * 16];
    __shared__ __align__(16) float sH3T[64 * 16];
    __shared__ float sBase[TS];
    __shared__ float sPrice[TS];
    __shared__ int   sIdx[TS * 9];

    const int t  = threadIdx.x;
    const int w  = t >> 5;
    const int ln = t & 31;
    const int s0blk = blockIdx.x * TS;

    // ---- on-device input-layout detection (deterministic, data-driven) ----
    const unsigned long long* u0 = (const unsigned long long*)a.p[0];
    const bool is64 = ((u0[0] | u0[1] | u0[2] | u0[3]) < (1ULL << 20));
    const unsigned long long* u7 = (const unsigned long long*)a.p[7];
    const bool dict = (u7[0] < (1ULL << 40));   // slot7 small ints => hour (dict order)

    const void* idp[9];
    #pragma unroll
    for (int f = 0; f < 7; f++) idp[f] = a.p[f];
    const float* price;
    if (dict) { idp[7] = a.p[7]; idp[8] = a.p[8]; price = (const float*)a.p[9]; }
    else      { price = (const float*)a.p[7]; idp[7] = a.p[8]; idp[8] = a.p[9]; }

    const float* emb[9];
    #pragma unroll
    for (int f = 0; f < 9; f++) emb[f] = (const float*)a.p[10 + f];
    const float* __restrict__ w_dense = (const float*)a.p[19];
    const float* __restrict__ b_dense = (const float*)a.p[20];
    const float* __restrict__ fm_v    = (const float*)a.p[21];
    const float* __restrict__ W1 = (const float*)a.p[22];
    const float* __restrict__ b1 = (const float*)a.p[23];
    const float* __restrict__ W2 = (const float*)a.p[24];
    const float* __restrict__ b2 = (const float*)a.p[25];
    const float* __restrict__ W3 = (const float*)a.p[26];
    const float* __restrict__ b3 = (const float*)a.p[27];
    const float* __restrict__ Wo = (const float*)a.p[28];
    const float* __restrict__ bo = (const float*)a.p[29];

    // ---- Phase A: gather ids + price ----
    if (t < TS * 9) {
        int s = t / 9, f = t - s * 9;
        sIdx[s * 9 + f] = read_id(idp[f], s0blk + s, is64);
    }
    if (t >= 224 && t < 224 + TS) sPrice[t - 224] = price[s0blk + (t - 224)];
    __syncthreads();

    // ---- Phase C: build transposed deep_in XT[77][16] ----
    for (int idx = t; idx < TS * 77; idx += NT) {
        int s = idx & 15, c = idx >> 4;
        float v;
        if (c == 76) v = sPrice[s];
        else {
            int f = 8;
            #pragma unroll
            for (int k = 8; k >= 1; k--) if (c < c_EOFF[k]) f = k - 1;
            int e = c - c_EOFF[f];
            v = emb[f][sIdx[s * 9 + f] * c_EDIM[f] + e];
        }
        sXT[c * 16 + s] = v;
    }

    // ---- Phase B: FM 2nd order + dense 1st order (half-warp per sample, E=16) ----
    {
        int s = w * 2 + (ln >> 4);
        int e = ln & 15;
        float pv = sPrice[s] * 1e-3f;
        float fs = 0.f, ss = 0.f;
        #pragma unroll
        for (int f = 0; f < 9; f++) {
            int row = c_FOFF[f] + sIdx[s * 9 + f];
            float v = fm_v[row * 16 + e];
            fs += v; ss += v * v;
        }
        {
            float v = fm_v[NF_LAST * 16 + e];
            fs += pv * v; ss += pv * pv * v * v;
        }
        float val = fs * fs - ss;
        #pragma unroll
        for (int o = 8; o; o >>= 1) val += __shfl_xor_sync(0xffffffffu, val, o, 16);
        float fm = 0.5f * val;

        float dn = 0.f;
        if (e < 9)  dn = w_dense[c_FOFF[e] + sIdx[s * 9 + e]];
        if (e == 9) dn = pv * w_dense[NF_LAST];
        #pragma unroll
        for (int o = 8; o; o >>= 1) dn += __shfl_xor_sync(0xffffffffu, dn, o, 16);

        if (e == 0) sBase[s] = fm + dn + b_dense[0];
    }
    __syncthreads();

    // ---- Layer 1: H1 = relu(X @ W1 + b1), K=77, N=256 ----
    // thread tile: 4 outs x 4 samples. lane = sg(4 groups) * 8 + jgl(8).
    // weight float4 addresses within a warp: 8 consecutive 16B = 128B, shared by 4 sg lanes.
    {
        int sg  = ln >> 3;                 // 0..3 -> samples sg*4..sg*4+3
        int jgl = ln & 7;
        int j0  = (w * 8 + jgl) * 4;       // 0..252
        int s0  = sg * 4;
        float4 bv = *(const float4*)(b1 + j0);
        u64 acc[4][2];
        acc[0][0] = acc[0][1] = pack2(bv.x);
        acc[1][0] = acc[1][1] = pack2(bv.y);
        acc[2][0] = acc[2][1] = pack2(bv.z);
        acc[3][0] = acc[3][1] = pack2(bv.w);
        #pragma unroll 7
        for (int i = 0; i < 77; i++) {
            float4 wv = *(const float4*)(W1 + i * 256 + j0);
            double2 xv = *(const double2*)(sXT + i * 16 + s0);
            u64 x01 = __double_as_longlong(xv.x);
            u64 x23 = __double_as_longlong(xv.y);
            u64 w0 = pack2(wv.x), w1p = pack2(wv.y), w2p = pack2(wv.z), w3p = pack2(wv.w);
            ffma2(acc[0][0], w0,  x01); ffma2(acc[0][1], w0,  x23);
            ffma2(acc[1][0], w1p, x01); ffma2(acc[1][1], w1p, x23);
            ffma2(acc[2][0], w2p, x01); ffma2(acc[2][1], w2p, x23);
            ffma2(acc[3][0], w3p, x01); ffma2(acc[3][1], w3p, x23);
        }
        #pragma unroll
        for (int j = 0; j < 4; j++) {
            float2 lo = unpack2(acc[j][0]);
            float2 hi = unpack2(acc[j][1]);
            float4 o;
            o.x = fmaxf(lo.x, 0.f); o.y = fmaxf(lo.y, 0.f);
            o.z = fmaxf(hi.x, 0.f); o.w = fmaxf(hi.y, 0.f);
            *(float4*)(sH1T + (j0 + j) * 16 + s0) = o;
        }
    }
    __syncthreads();

    // ---- Layer 2: H2 = relu(H1 @ W2 + b2), K=256, N=128 ----
    // thread tile: 2 outs x 4 samples. weight float2 per iter: warp covers 64B, dedup by sg.
    {
        int sg  = ln >> 3;
        int jgl = ln & 7;
        int j0  = (w * 8 + jgl) * 2;       // 0..126
        int s0  = sg * 4;
        float2 bv = *(const float2*)(b2 + j0);
        u64 acc[2][2];
        acc[0][0] = acc[0][1] = pack2(bv.x);
        acc[1][0] = acc[1][1] = pack2(bv.y);
        #pragma unroll 8
        for (int i = 0; i < 256; i++) {
            float2 wv = *(const float2*)(W2 + i * 128 + j0);
            double2 xv = *(const double2*)(sH1T + i * 16 + s0);
            u64 x01 = __double_as_longlong(xv.x);
            u64 x23 = __double_as_longlong(xv.y);
            u64 w0 = pack2(wv.x), w1p = pack2(wv.y);
            ffma2(acc[0][0], w0,  x01); ffma2(acc[0][1], w0,  x23);
            ffma2(acc[1][0], w1p, x01); ffma2(acc[1][1], w1p, x23);
        }
        #pragma unroll
        for (int j = 0; j < 2; j++) {
            float2 lo = unpack2(acc[j][0]);
            float2 hi = unpack2(acc[j][1]);
            float4 o;
            o.x = fmaxf(lo.x, 0.f); o.y = fmaxf(lo.y, 0.f);
            o.z = fmaxf(hi.x, 0.f); o.w = fmaxf(hi.y, 0.f);
            *(float4*)(sH2T + (j0 + j) * 16 + s0) = o;
        }
    }
    __syncthreads();

    // ---- Layer 3: H3 = relu(H2 @ W3 + b3), K=128, N=64 ----
    // thread tile: 1 out x 4 samples. weight scalar: warp covers 32B, dedup by sg.
    {
        int sg = ln >> 3;
        int jl = ln & 7;
        int j  = w * 8 + jl;               // 0..63
        int s0 = sg * 4;
        u64 acc0, acc1;
        acc0 = acc1 = pack2(b3[j]);
        #pragma unroll 8
        for (int i = 0; i < 128; i++) {
            float wv = W3[i * 64 + j];
            double2 xv = *(const double2*)(sH2T + i * 16 + s0);
            u64 wp = pack2(wv);
            ffma2(acc0, wp, __double_as_longlong(xv.x));
            ffma2(acc1, wp, __double_as_longlong(xv.y));
        }
        float2 lo = unpack2(acc0);
        float2 hi = unpack2(acc1);
        float4 o;
        o.x = fmaxf(lo.x, 0.f); o.y = fmaxf(lo.y, 0.f);
        o.z = fmaxf(hi.x, 0.f); o.w = fmaxf(hi.y, 0.f);
        *(float4*)(sH3T + j * 16 + s0) = o;
    }
    __syncthreads();

    // ---- Output: out[s] = H3[s] . Wo + bo + base ----
    if (t < TS) {
        int s = t;
        float v0 = 0.f, v1 = 0.f, v2 = 0.f, v3 = 0.f;
        #pragma unroll
        for (int j = 0; j < 64; j += 4) {
            v0 += sH3T[(j    ) * 16 + s] * Wo[j    ];
            v1 += sH3T[(j + 1) * 16 + s] * Wo[j + 1];
            v2 += sH3T[(j + 2) * 16 + s] * Wo[j + 2];
            v3 += sH3T[(j + 3) * 16 + s] * Wo[j + 3];
        }
        if (s0blk + s < B)
            out[s0blk + s] = (v0 + v1) + (v2 + v3) + bo[0] + sBase[s];
    }
}

extern "C" void kernel_launch(void* const* d_in, const int* in_sizes, int n_in,
                              void* d_out, int out_size)
{
    (void)in_sizes; (void)n_in;
    P30 a;
    for (int i = 0; i < 30; i++) a.p[i] = d_in[i];
    deepfm_kernel<<<NBLK, NT>>>(a, (float*)d_out, out_size);
}